// round 16
// baseline (speedup 1.0000x reference)
#include <cuda_runtime.h>
#include <math_constants.h>
#include <math.h>

#define BB 8
#define QQ 2048
#define TT 256
#define NTHR 256
#define NWARP (NTHR/32)

// Scratch
__device__ float g_cost[(size_t)BB * TT * QQ];   // transposed cost [b][t][q]
__device__ float g_prob[(size_t)BB * QQ];        // softmax probs

// ---------------------------------------------------------------------------
// Cephes exp, strict IEEE f32 (proven invariance class: R9/R10/R13/R14
// all bit-identical in outcome; __nv_expf is in the same class).
// ---------------------------------------------------------------------------
__device__ __forceinline__ float xla_exp(float x) {
    x = fminf(x, 88.3762626647950f);
    x = fmaxf(x, -88.3762626647949f);
    float fx = __fadd_rn(__fmul_rn(x, 1.44269504088896341f), 0.5f);
    fx = floorf(fx);
    float tmp = __fmul_rn(fx, 0.693359375f);
    float z   = __fmul_rn(fx, -2.12194440e-4f);
    x = __fsub_rn(x, tmp);
    x = __fsub_rn(x, z);
    z = __fmul_rn(x, x);
    float y = 1.9875691500e-4f;
    y = __fadd_rn(__fmul_rn(y, x), 1.3981999507e-3f);
    y = __fadd_rn(__fmul_rn(y, x), 8.3334519073e-3f);
    y = __fadd_rn(__fmul_rn(y, x), 4.1665795894e-2f);
    y = __fadd_rn(__fmul_rn(y, x), 1.6666665459e-1f);
    y = __fadd_rn(__fmul_rn(y, x), 5.0000001201e-1f);
    y = __fadd_rn(__fmul_rn(y, z), x);
    y = __fadd_rn(y, 1.0f);
    int n = (int)fx;
    float p = __int_as_float((n + 127) << 23);
    return __fmul_rn(y, p);
}

// ---------------------------------------------------------------------------
// Per-batch softmax over Q of channel 0.
// Denominator: XLA:GPU row-reduction order (256 threads/row):
//   partial[t] = sum_{k=0}^{7} se[t + 256k]          (k ascending, f32)
//   per warp w: shuffle-down tree, offsets 16,8,4,2,1
//   inter-warp: 8 warp sums, tree offsets 4,2,1
// Association replicated exactly (serial tid0 tree over shared partials).
// ---------------------------------------------------------------------------
__global__ __launch_bounds__(256)
void softmax_kernel(const float* __restrict__ outputs) {
    int b = blockIdx.x, tid = threadIdx.x;
    __shared__ float red[256];
    __shared__ float se[QQ];
    __shared__ float part[256];
    __shared__ float s_den;

    float m = -CUDART_INF_F;
    for (int q = tid; q < QQ; q += 256)
        m = fmaxf(m, outputs[((size_t)b * QQ + q) * 3]);
    red[tid] = m; __syncthreads();
    for (int s = 128; s > 0; s >>= 1) {
        if (tid < s) red[tid] = fmaxf(red[tid], red[tid + s]);
        __syncthreads();
    }
    float mx = red[0];
    __syncthreads();

    for (int q = tid; q < QQ; q += 256)
        se[q] = xla_exp(__fsub_rn(outputs[((size_t)b * QQ + q) * 3], mx));
    __syncthreads();

    {   // per-thread strided partial, k ascending
        float pp = 0.f;
#pragma unroll
        for (int k = 0; k < QQ / 256; k++)
            pp = __fadd_rn(pp, se[tid + 256 * k]);
        part[tid] = pp;
    }
    __syncthreads();
    if (tid == 0) {   // exact tree association, serial
        float w[8];
        for (int wd = 0; wd < 8; wd++) {
            float q[32];
            for (int l = 0; l < 32; l++) q[l] = part[wd * 32 + l];
            for (int off = 16; off > 0; off >>= 1)
                for (int l = 0; l < off; l++)
                    q[l] = __fadd_rn(q[l], q[l + off]);
            w[wd] = q[0];
        }
        for (int off = 4; off > 0; off >>= 1)
            for (int l = 0; l < off; l++)
                w[l] = __fadd_rn(w[l], w[l + off]);
        s_den = w[0];
    }
    __syncthreads();
    float den = s_den;

    for (int q = tid; q < QQ; q += 256)
        g_prob[(size_t)b * QQ + q] = __fdiv_rn(se[q], den);
}

// ---------------------------------------------------------------------------
// Build transposed cost blocks: g_cost[b][t][q] = -prob[b][q] + L1(pos)
// ---------------------------------------------------------------------------
__global__ __launch_bounds__(256)
void build_cost_kernel(const float* __restrict__ outputs,
                       const float* __restrict__ targets) {
    int idx = blockIdx.x * blockDim.x + threadIdx.x;     // < 2^22
    if (idx >= BB * TT * QQ) return;
    int q = idx & (QQ - 1);
    int t = (idx >> 11) & (TT - 1);
    int b = idx >> 19;

    const float* o  = outputs + ((size_t)b * QQ + q) * 3;
    const float* tg = targets + ((size_t)b * TT + t) * 3;
    float prob = g_prob[(size_t)b * QQ + q];
    float l1 = __fadd_rn(fabsf(__fsub_rn(o[1], tg[1])), fabsf(__fsub_rn(o[2], tg[2])));
    g_cost[idx] = __fadd_rn(-prob, l1);
}

// ---------------------------------------------------------------------------
// Reference-faithful JV variant (non-persistent minv). One block per batch.
// Double duals, first-index tie-break. Output float32.
// ---------------------------------------------------------------------------
__global__ __launch_bounds__(NTHR)
void lsa_kernel(float* __restrict__ out) {
    __shared__ double vv[QQ + 1];
    __shared__ double u[TT + 1];
    __shared__ int    p[QQ + 1];
    __shared__ unsigned char used[QQ + 1];
    __shared__ int    chain[TT + 2];
    __shared__ double wr_val[NWARP];
    __shared__ int    wr_idx[NWARP];
    __shared__ double s_delta;
    __shared__ int    s_j1;
    __shared__ int    cnt[NTHR];

    const int b = blockIdx.x, tid = threadIdx.x;
    const float* cost = g_cost + (size_t)b * TT * QQ;

    for (int k = tid; k < TT; k += NTHR) {
        out[b * TT + k]           = (float)k;
        out[BB * TT + b * TT + k] = (float)k;
    }

    for (int j = tid; j <= QQ; j += NTHR) { vv[j] = 0.0; p[j] = 0; used[j] = 0; }
    for (int k = tid; k <= TT; k += NTHR) u[k] = 0.0;
    __syncthreads();

    const unsigned full = 0xffffffffu;

    for (int i = 1; i <= TT; i++) {
        if (tid == 0) p[0] = i;
        int j0 = 0;
        int len = 0;
        int ok = 1;
        __syncthreads();

        while (true) {
            if (tid == 0) { used[j0] = 1; chain[len] = j0; }
            len++;
            __syncthreads();

            const int i0 = p[j0];
            const double ui0 = u[i0];
            const float* crow = cost + (size_t)(i0 - 1) * QQ;

            double best = CUDART_INF;
            int bidx = QQ + 2;
#pragma unroll
            for (int jj = 0; jj < QQ / NTHR; jj++) {
                int j = 1 + tid + jj * NTHR;
                if (!used[j]) {
                    double cur = ((double)crow[j - 1] - ui0) - vv[j];
                    if (cur < best) { best = cur; bidx = j; }
                }
            }
            for (int off = 16; off > 0; off >>= 1) {
                double ov = __shfl_down_sync(full, best, off);
                int    oi = __shfl_down_sync(full, bidx, off);
                if (ov < best || (ov == best && oi < bidx)) { best = ov; bidx = oi; }
            }
            if ((tid & 31) == 0) { wr_val[tid >> 5] = best; wr_idx[tid >> 5] = bidx; }
            __syncthreads();
            if (tid < 32) {
                double bv = (tid < NWARP) ? wr_val[tid] : CUDART_INF;
                int    bi = (tid < NWARP) ? wr_idx[tid] : QQ + 2;
                for (int off = NWARP / 2; off > 0; off >>= 1) {
                    double ov = __shfl_down_sync(full, bv, off);
                    int    oi = __shfl_down_sync(full, bi, off);
                    if (ov < bv || (ov == bv && oi < bi)) { bv = ov; bi = oi; }
                }
                if (tid == 0) { s_delta = bv; s_j1 = bi; }
            }
            __syncthreads();
            const double delta = s_delta;
            const int j1 = s_j1;

            if (j1 < 1 || j1 > QQ || len > TT) { ok = 0; break; }

            if (tid < len) {
                int jc = chain[tid];
                u[p[jc]] += delta;
                if (jc > 0) vv[jc] -= delta;
            }

            j0 = j1;
            if (p[j0] == 0) break;
            __syncthreads();
        }

        __syncthreads();
        if (ok && tid == 0) {
            int jf = j0;
            for (int t = len - 1; t >= 0; t--) { p[jf] = p[chain[t]]; jf = chain[t]; }
        }
        if (tid < len) { int jc = chain[tid]; if (jc > 0 && jc <= QQ) used[jc] = 0; }
        __syncthreads();
    }

    {
        const int jbase = 1 + tid * (QQ / NTHR);
        int c = 0;
#pragma unroll
        for (int k = 0; k < QQ / NTHR; k++) c += (p[jbase + k] > 0);
        cnt[tid] = c;
        __syncthreads();
        for (int off = 1; off < NTHR; off <<= 1) {
            int vprev = (tid >= off) ? cnt[tid - off] : 0;
            __syncthreads();
            cnt[tid] += vprev;
            __syncthreads();
        }
        int pos = cnt[tid] - c;
#pragma unroll
        for (int k = 0; k < QQ / NTHR; k++) {
            int j = jbase + k;
            int pj = p[j];
            if (pj > 0 && pos < TT) {
                out[b * TT + pos]           = (float)(j - 1);
                out[BB * TT + b * TT + pos] = (float)(pj - 1);
                pos++;
            }
        }
    }
}

// ---------------------------------------------------------------------------
extern "C" void kernel_launch(void* const* d_in, const int* in_sizes, int n_in,
                              void* d_out, int out_size) {
    const float* outputs = (const float*)d_in[0];
    const float* targets = (const float*)d_in[1];
    if (n_in >= 2 && in_sizes[0] == BB * TT * 3 && in_sizes[1] == BB * QQ * 3) {
        outputs = (const float*)d_in[1];
        targets = (const float*)d_in[0];
    }
    float* out = (float*)d_out;            // [2][B][T], float32

    softmax_kernel<<<BB, 256>>>(outputs);
    build_cost_kernel<<<(BB * TT * QQ) / 256, 256>>>(outputs, targets);
    lsa_kernel<<<BB, NTHR>>>(out);
}